// round 10
// baseline (speedup 1.0000x reference)
#include <cuda_runtime.h>
#include <cuda_bf16.h>
#include <stdint.h>
#include <math.h>

#define B_  64
#define T_  512
#define E_  512
#define H_  256
#define NT_ 20
#define HBUF (16 * 264 * 2)   /* bytes per h buffer */

// ---------------- scratch (device globals) ------------------------------------
__device__ __nv_bfloat16 g_xbfA[B_ * T_ * E_];        // 32 MB  layer-0 input (bf16)
__device__ __nv_bfloat16 g_xbfB[B_ * T_ * E_];        // 32 MB  layer-1 input (bf16)
__device__ float g_xA[B_ * T_ * E_];                  // 64 MB  final layer output (fp32)
__device__ float g_xg[(size_t)B_ * T_ * 2048];        // 256 MB input projections
__device__ __nv_bfloat16 g_wbf[2 * 2048 * E_];        // 4 MB   w_ih in bf16
__device__ float g_em[B_ * T_ * NT_];
__device__ float g_llh[B_];

// ---------------- small helpers ------------------------------------------------
__device__ __forceinline__ unsigned pack_bf2(float a, float b) {
    __nv_bfloat162 h2 = __floats2bfloat162_rn(a, b);
    return *reinterpret_cast<unsigned*>(&h2);
}
__device__ __forceinline__ void ldsm4(unsigned& a0, unsigned& a1, unsigned& a2, unsigned& a3,
                                      unsigned addr) {
    asm volatile("ldmatrix.sync.aligned.m8n8.x4.shared.b16 {%0,%1,%2,%3}, [%4];\n"
                 : "=r"(a0), "=r"(a1), "=r"(a2), "=r"(a3) : "r"(addr));
}
__device__ __forceinline__ void mma_bf(float& d0, float& d1, float& d2, float& d3,
                                       unsigned a0, unsigned a1, unsigned a2, unsigned a3,
                                       unsigned b0, unsigned b1) {
    asm volatile("mma.sync.aligned.m16n8k16.row.col.f32.bf16.bf16.f32 "
                 "{%0,%1,%2,%3},{%4,%5,%6,%7},{%8,%9},{%0,%1,%2,%3};\n"
                 : "+f"(d0), "+f"(d1), "+f"(d2), "+f"(d3)
                 : "r"(a0), "r"(a1), "r"(a2), "r"(a3), "r"(b0), "r"(b1));
}
__device__ __forceinline__ unsigned mapa_u32(unsigned addr, int rank) {
    unsigned out;
    asm("mapa.shared::cluster.u32 %0, %1, %2;" : "=r"(out) : "r"(addr), "r"(rank));
    return out;
}
__device__ __forceinline__ void st_dsm64(unsigned addr, unsigned long long v) {
    asm volatile("st.shared::cluster.b64 [%0], %1;" :: "r"(addr), "l"(v) : "memory");
}
__device__ __forceinline__ float tanhfast(float x) {
    float y;
    asm("tanh.approx.f32 %0, %1;" : "=f"(y) : "f"(x));
    return y;
}
__device__ __forceinline__ float sigm(float x) { return 0.5f * tanhfast(0.5f * x) + 0.5f; }

// ---------------- conversion / gather ------------------------------------------
__global__ void k_wcvt(const float* __restrict__ w_ih) {
    int i = (blockIdx.x * 256 + threadIdx.x) * 4;
    float4 v = *(const float4*)(w_ih + i);
    uint2 o;
    o.x = pack_bf2(v.x, v.y);
    o.y = pack_bf2(v.z, v.w);
    *(uint2*)(g_wbf + i) = o;
}

__global__ void k_gather(const int* __restrict__ ids, const float* __restrict__ embed) {
    int bt = blockIdx.x;
    int id = ids[bt];
    int e = threadIdx.x * 4;
    float4 v = *(const float4*)(embed + (size_t)id * E_ + e);
    uint2 o;
    o.x = pack_bf2(v.x, v.y);
    o.y = pack_bf2(v.z, v.w);
    *(uint2*)(g_xbfA + (size_t)bt * E_ + e) = o;
}

// ---------------- bf16 tensor-core GEMM: xg = X @ W^T + bias -------------------
__global__ void __launch_bounds__(256) k_gemm_bf(const float* __restrict__ b_ih,
                                                 const float* __restrict__ b_hh,
                                                 int layer) {
    __shared__ __align__(16) __nv_bfloat16 As[128 * 40];
    __shared__ __align__(16) __nv_bfloat16 Bs[128 * 40];

    const __nv_bfloat16* Xbf = layer ? g_xbfB : g_xbfA;
    const __nv_bfloat16* Wbf = g_wbf + (size_t)layer * 2048 * E_;
    const float* bi = b_ih + layer * 2048;
    const float* bh = b_hh + layer * 2048;

    int m0 = blockIdx.y * 128, n0 = blockIdx.x * 128;
    int tid = threadIdx.x, w = tid >> 5, lane = tid & 31;

    const __nv_bfloat16* Ag = Xbf + (size_t)(m0 + (tid >> 2)) * E_ + (tid & 3) * 8;
    const __nv_bfloat16* Bg = Wbf + (size_t)(n0 + (tid >> 2)) * E_ + (tid & 3) * 8;
    int soff = (tid >> 2) * 40 + (tid & 3) * 8;

    unsigned a_base = (unsigned)__cvta_generic_to_shared(As);
    unsigned b_base = (unsigned)__cvta_generic_to_shared(Bs);

    int mbase = (w & 1) * 64, nbase = (w >> 1) * 32;

    float acc[4][4][4];
#pragma unroll
    for (int i = 0; i < 4; i++)
#pragma unroll
        for (int j = 0; j < 4; j++)
#pragma unroll
            for (int r = 0; r < 4; r++) acc[i][j][r] = 0.f;

    uint4 ra[2], rb[2];
#pragma unroll
    for (int i = 0; i < 2; i++) {
        ra[i] = *(const uint4*)(Ag + i * 64 * E_);
        rb[i] = *(const uint4*)(Bg + i * 64 * E_);
    }

    for (int kb = 0; kb < 16; ++kb) {
#pragma unroll
        for (int i = 0; i < 2; i++) {
            *(uint4*)&As[soff + i * 64 * 40] = ra[i];
            *(uint4*)&Bs[soff + i * 64 * 40] = rb[i];
        }
        __syncthreads();
        if (kb < 15) {
#pragma unroll
            for (int i = 0; i < 2; i++) {
                ra[i] = *(const uint4*)(Ag + (kb + 1) * 32 + i * 64 * E_);
                rb[i] = *(const uint4*)(Bg + (kb + 1) * 32 + i * 64 * E_);
            }
        }
#pragma unroll
        for (int kk = 0; kk < 32; kk += 16) {
            unsigned aF[4][4], bF[4][2];
#pragma unroll
            for (int mt = 0; mt < 4; ++mt) {
                int row = mbase + mt * 16 + (lane & 15);
                int col = kk + ((lane >> 4) << 3);
                ldsm4(aF[mt][0], aF[mt][1], aF[mt][2], aF[mt][3],
                      a_base + (unsigned)(row * 40 + col) * 2);
            }
#pragma unroll
            for (int p = 0; p < 2; ++p) {
                int row = nbase + 16 * p + ((lane >> 4) << 3) + (lane & 7);
                int colb = kk + (((lane >> 3) & 1) << 3);
                ldsm4(bF[2 * p][0], bF[2 * p][1], bF[2 * p + 1][0], bF[2 * p + 1][1],
                      b_base + (unsigned)(row * 40 + colb) * 2);
            }
#pragma unroll
            for (int mt = 0; mt < 4; ++mt)
#pragma unroll
                for (int nt = 0; nt < 4; ++nt)
                    mma_bf(acc[mt][nt][0], acc[mt][nt][1], acc[mt][nt][2], acc[mt][nt][3],
                           aF[mt][0], aF[mt][1], aF[mt][2], aF[mt][3],
                           bF[nt][0], bF[nt][1]);
        }
        __syncthreads();
    }

#pragma unroll
    for (int nt = 0; nt < 4; ++nt) {
        int coln = n0 + nbase + 8 * nt + 2 * (lane & 3);
        float bb0 = bi[coln] + bh[coln];
        float bb1 = bi[coln + 1] + bh[coln + 1];
#pragma unroll
        for (int mt = 0; mt < 4; ++mt) {
            int row = m0 + mbase + 16 * mt + (lane >> 2);
            *(float2*)&g_xg[(size_t)row * 2048 + coln] =
                make_float2(acc[mt][nt][0] + bb0, acc[mt][nt][1] + bb1);
            *(float2*)&g_xg[(size_t)(row + 8) * 2048 + coln] =
                make_float2(acc[mt][nt][2] + bb0, acc[mt][nt][3] + bb1);
        }
    }
}

// ---------------- persistent BiLSTM layer: BOTH dirs per CTA -------------------
// 32 CTAs = 4 clusters of 8.  Cluster = batch-block of 16, both directions.
// CTA rank ub owns units [ub*32, ub*32+32) for dir 0 AND dir 1 (B-frags for
// both in registers).  ONE cluster barrier per step covers both dirs'
// exchanges — halves barrier count per dir-step vs round 8.
__global__ void __launch_bounds__(256, 1) __cluster_dims__(8, 1, 1)
k_lstm(const float* __restrict__ w_hh, const int* __restrict__ lengths,
       int layer, int out_fp32) {
    __shared__ __align__(16) __nv_bfloat16 h_shD[4][16 * 264]; // [dir*2+parity]
    __shared__ __align__(16) unsigned long long h_own[2][8][16];
    __shared__ int len_sh[16];

    int cta = blockIdx.x;
    int ub  = cta & 7;          // cluster rank
    int bb  = cta >> 3;         // batch-block 0..3
    int tid = threadIdx.x;
    int w = tid >> 5, lane = tid & 31;

    // ---- B fragments for BOTH dirs: warp w = units {4w..4w+3} x gates {0..3} ----
    unsigned bfr0[16][2][2], bfr1[16][2][2];
    {
        int c2 = (lane & 3) * 2;
#pragma unroll
        for (int p = 0; p < 2; ++p) {
            int lc = 8 * p + (lane >> 2);
            int g = lc & 3, du = lc >> 2;
            size_t rowoff = (size_t)(g * 256 + ub * 32 + w * 4 + du) * 256;
            const float* wr0 = w_hh + (size_t)(layer * 2 + 0) * 1024 * 256 + rowoff;
            const float* wr1 = w_hh + (size_t)(layer * 2 + 1) * 1024 * 256 + rowoff;
#pragma unroll
            for (int kt = 0; kt < 16; ++kt) {
                bfr0[kt][p][0] = pack_bf2(wr0[kt * 16 + c2],     wr0[kt * 16 + c2 + 1]);
                bfr0[kt][p][1] = pack_bf2(wr0[kt * 16 + c2 + 8], wr0[kt * 16 + c2 + 9]);
                bfr1[kt][p][0] = pack_bf2(wr1[kt * 16 + c2],     wr1[kt * 16 + c2 + 1]);
                bfr1[kt][p][1] = pack_bf2(wr1[kt * 16 + c2 + 8], wr1[kt * 16 + c2 + 9]);
            }
        }
    }
    if (tid < 16) len_sh[tid] = lengths[bb * 16 + tid];
    // zero step-0 h state for both dirs (parity 0 buffers)
    for (int i = tid; i < 16 * 264 / 2; i += 256) {
        ((unsigned*)h_shD[0])[i] = 0u;
        ((unsigned*)h_shD[2])[i] = 0u;
    }
    __syncthreads();
    asm volatile("barrier.cluster.arrive.aligned;" ::: "memory");
    asm volatile("barrier.cluster.wait.aligned;" ::: "memory");

    int maxlen = 0;
#pragma unroll
    for (int i = 0; i < 16; i++) maxlen = max(maxlen, len_sh[i]);

    // gate mapping: thread (w, lane) -> batches r, r+8 ; unit 4w + du
    int q = lane & 3, r = lane >> 2;
    bool qe = (q & 1) == 0;
    int du = ((q & 1) << 1) | (q >> 1);
    int unit = ub * 32 + 4 * w + du;
    int len0 = len_sh[r], len1 = len_sh[r + 8];
    int gb0 = bb * 16 + r, gb1 = bb * 16 + r + 8;
    const float* xg0_d0 = g_xg + (size_t)gb0 * T_ * 2048 + unit;
    const float* xg1_d0 = g_xg + (size_t)gb1 * T_ * 2048 + unit;
    const float* xg0_d1 = xg0_d0 + 1024;
    const float* xg1_d1 = xg1_d0 + 1024;

    unsigned hsh_base = (unsigned)__cvta_generic_to_shared(&h_shD[0][0]);
    unsigned a_addr0 = hsh_base + (unsigned)(lane & 15) * 528 + ((lane >> 4) << 4);

    // push: lane's FIXED peer = lane&7; batches (lane>>3)+{0,4,8,12}
    int peer = lane & 7;
    unsigned dsm_peer = mapa_u32(hsh_base + (unsigned)((ub * 32 + 4 * w) * 2), peer);

    float cstA0 = 0.f, cstA1 = 0.f;   // dir0: batches r, r+8
    float cstB0 = 0.f, cstB1 = 0.f;   // dir1
    float xaD0[2][8], xaD1[2][8];

    // prefetch xg for s = 0 (both dirs)
    {
        const float* p00 = xg0_d0;
        const float* p10 = xg1_d0;
        const float* p01 = xg0_d1 + (size_t)(len0 - 1) * 2048;
        const float* p11 = xg1_d1 + (size_t)(len1 - 1) * 2048;
        xaD0[0][0] = p00[0]; xaD0[0][1] = p00[256]; xaD0[0][2] = p00[512]; xaD0[0][3] = p00[768];
        xaD0[0][4] = p10[0]; xaD0[0][5] = p10[256]; xaD0[0][6] = p10[512]; xaD0[0][7] = p10[768];
        xaD1[0][0] = p01[0]; xaD1[0][1] = p01[256]; xaD1[0][2] = p01[512]; xaD1[0][3] = p01[768];
        xaD1[0][4] = p11[0]; xaD1[0][5] = p11[256]; xaD1[0][6] = p11[512]; xaD1[0][7] = p11[768];
    }

    for (int s = 0; s < maxlen; ++s) {
        int p = s & 1;
        // ---- prefetch xg for s+1, both dirs ----
        if (s + 1 < maxlen) {
            int sn = s + 1;
            if (sn < len0) {
                const float* pp = xg0_d0 + (size_t)sn * 2048;
                xaD0[p ^ 1][0] = pp[0]; xaD0[p ^ 1][1] = pp[256];
                xaD0[p ^ 1][2] = pp[512]; xaD0[p ^ 1][3] = pp[768];
                const float* pb = xg0_d1 + (size_t)(len0 - 1 - sn) * 2048;
                xaD1[p ^ 1][0] = pb[0]; xaD1[p ^ 1][1] = pb[256];
                xaD1[p ^ 1][2] = pb[512]; xaD1[p ^ 1][3] = pb[768];
            }
            if (sn < len1) {
                const float* pp = xg1_d0 + (size_t)sn * 2048;
                xaD0[p ^ 1][4] = pp[0]; xaD0[p ^ 1][5] = pp[256];
                xaD0[p ^ 1][6] = pp[512]; xaD0[p ^ 1][7] = pp[768];
                const float* pb = xg1_d1 + (size_t)(len1 - 1 - sn) * 2048;
                xaD1[p ^ 1][4] = pb[0]; xaD1[p ^ 1][5] = pb[256];
                xaD1[p ^ 1][6] = pb[512]; xaD1[p ^ 1][7] = pb[768];
            }
        }

        // ---- wait: peers' pushes from step s-1 (both dirs) landed ----
        if (s > 0)
            asm volatile("barrier.cluster.wait.aligned;" ::: "memory");

        // ---- recurrent mma, both dirs (4 independent accumulator chains) ----
        unsigned aaD0 = a_addr0 + (unsigned)p * HBUF;
        unsigned aaD1 = a_addr0 + (unsigned)(2 + p) * HBUF;
        float ac0[2][4], ac1[2][4];
#pragma unroll
        for (int t = 0; t < 2; ++t)
#pragma unroll
            for (int i = 0; i < 4; ++i) { ac0[t][i] = 0.f; ac1[t][i] = 0.f; }
#pragma unroll
        for (int kt = 0; kt < 16; ++kt) {
            unsigned A0, A1, A2, A3;
            ldsm4(A0, A1, A2, A3, aaD0 + kt * 32);
            mma_bf(ac0[0][0], ac0[0][1], ac0[0][2], ac0[0][3],
                   A0, A1, A2, A3, bfr0[kt][0][0], bfr0[kt][0][1]);
            mma_bf(ac0[1][0], ac0[1][1], ac0[1][2], ac0[1][3],
                   A0, A1, A2, A3, bfr0[kt][1][0], bfr0[kt][1][1]);
            unsigned B0, B1, B2, B3;
            ldsm4(B0, B1, B2, B3, aaD1 + kt * 32);
            mma_bf(ac1[0][0], ac1[0][1], ac1[0][2], ac1[0][3],
                   B0, B1, B2, B3, bfr1[kt][0][0], bfr1[kt][0][1]);
            mma_bf(ac1[1][0], ac1[1][1], ac1[1][2], ac1[1][3],
                   B0, B1, B2, B3, bfr1[kt][1][0], bfr1[kt][1][1]);
        }

        bool v0 = s < len0, v1 = s < len1;
        float hvA0 = 0.f, hvA1 = 0.f, hvB0 = 0.f, hvB1 = 0.f;

        // ---- dir 0: lane-pair exchange + gates ----
        {
            float own[4], rcv[4];
#pragma unroll
            for (int i = 0; i < 4; ++i) {
                float snd = qe ? ac0[1][i] : ac0[0][i];
                rcv[i] = __shfl_xor_sync(0xFFFFFFFFu, snd, 1);
                own[i] = qe ? ac0[0][i] : ac0[1][i];
            }
            float ai0 = (qe ? own[0] : rcv[0]) + xaD0[p][0];
            float af0 = (qe ? own[1] : rcv[1]) + xaD0[p][1];
            float ag0 = (qe ? rcv[0] : own[0]) + xaD0[p][2];
            float ao0 = (qe ? rcv[1] : own[1]) + xaD0[p][3];
            float ai1 = (qe ? own[2] : rcv[2]) + xaD0[p][4];
            float af1 = (qe ? own[3] : rcv[3]) + xaD0[p][5];
            float ag1 = (qe ? rcv[2] : own[2]) + xaD0[p][6];
            float ao1 = (qe ? rcv[3] : own[3]) + xaD0[p][7];
            if (v0) {
                cstA0 = sigm(af0) * cstA0 + sigm(ai0) * tanhfast(ag0);
                hvA0 = sigm(ao0) * tanhfast(cstA0);
                ((__nv_bfloat16*)&h_own[0][w][r])[du] = __float2bfloat16(hvA0);
            }
            if (v1) {
                cstA1 = sigm(af1) * cstA1 + sigm(ai1) * tanhfast(ag1);
                hvA1 = sigm(ao1) * tanhfast(cstA1);
                ((__nv_bfloat16*)&h_own[0][w][r + 8])[du] = __float2bfloat16(hvA1);
            }
        }
        // ---- dir 1 ----
        {
            float own[4], rcv[4];
#pragma unroll
            for (int i = 0; i < 4; ++i) {
                float snd = qe ? ac1[1][i] : ac1[0][i];
                rcv[i] = __shfl_xor_sync(0xFFFFFFFFu, snd, 1);
                own[i] = qe ? ac1[0][i] : ac1[1][i];
            }
            float ai0 = (qe ? own[0] : rcv[0]) + xaD1[p][0];
            float af0 = (qe ? own[1] : rcv[1]) + xaD1[p][1];
            float ag0 = (qe ? rcv[0] : own[0]) + xaD1[p][2];
            float ao0 = (qe ? rcv[1] : own[1]) + xaD1[p][3];
            float ai1 = (qe ? own[2] : rcv[2]) + xaD1[p][4];
            float af1 = (qe ? own[3] : rcv[3]) + xaD1[p][5];
            float ag1 = (qe ? rcv[2] : own[2]) + xaD1[p][6];
            float ao1 = (qe ? rcv[3] : own[3]) + xaD1[p][7];
            if (v0) {
                cstB0 = sigm(af0) * cstB0 + sigm(ai0) * tanhfast(ag0);
                hvB0 = sigm(ao0) * tanhfast(cstB0);
                ((__nv_bfloat16*)&h_own[1][w][r])[du] = __float2bfloat16(hvB0);
            }
            if (v1) {
                cstB1 = sigm(af1) * cstB1 + sigm(ai1) * tanhfast(ag1);
                hvB1 = sigm(ao1) * tanhfast(cstB1);
                ((__nv_bfloat16*)&h_own[1][w][r + 8])[du] = __float2bfloat16(hvB1);
            }
        }
        __syncwarp();

        // ---- push both dirs' slices; ONE arrive covers both ----
        if (s + 1 < maxlen) {
            int pn = p ^ 1;
            unsigned d0base = dsm_peer + (unsigned)pn * HBUF;
            unsigned d1base = dsm_peer + (unsigned)(2 + pn) * HBUF;
#pragma unroll
            for (int j = 0; j < 4; ++j) {
                int batch = (lane >> 3) + 4 * j;
                st_dsm64(d0base + (unsigned)batch * 528, h_own[0][w][batch]);
                st_dsm64(d1base + (unsigned)batch * 528, h_own[1][w][batch]);
            }
            asm volatile("barrier.cluster.arrive.aligned;" ::: "memory");
        }

        // ---- off critical path: write layer outputs (both dirs) ----
        if (v0) {
            size_t base0 = ((size_t)gb0 * T_ + s) * E_;
            size_t base0b = ((size_t)gb0 * T_ + (len0 - 1 - s)) * E_ + H_;
            if (out_fp32) { g_xA[base0 + unit] = hvA0; g_xA[base0b + unit] = hvB0; }
            else { g_xbfB[base0 + unit] = __float2bfloat16(hvA0);
                   g_xbfB[base0b + unit] = __float2bfloat16(hvB0); }
        }
        if (v1) {
            size_t base1 = ((size_t)gb1 * T_ + s) * E_;
            size_t base1b = ((size_t)gb1 * T_ + (len1 - 1 - s)) * E_ + H_;
            if (out_fp32) { g_xA[base1 + unit] = hvA1; g_xA[base1b + unit] = hvB1; }
            else { g_xbfB[base1 + unit] = __float2bfloat16(hvA1);
                   g_xbfB[base1b + unit] = __float2bfloat16(hvB1); }
        }
    }

    // ---- fused tail zeroing: positions t in [len, T), both dirs ----
    for (int t = len0; t < T_; ++t) {
        size_t xoff = ((size_t)gb0 * T_ + t) * E_ + unit;
        if (out_fp32) { g_xA[xoff] = 0.f; g_xA[xoff + H_] = 0.f; }
        else { g_xbfB[xoff] = __float2bfloat16(0.f);
               g_xbfB[xoff + H_] = __float2bfloat16(0.f); }
    }
    for (int t = len1; t < T_; ++t) {
        size_t xoff = ((size_t)gb1 * T_ + t) * E_ + unit;
        if (out_fp32) { g_xA[xoff] = 0.f; g_xA[xoff + H_] = 0.f; }
        else { g_xbfB[xoff] = __float2bfloat16(0.f);
               g_xbfB[xoff + H_] = __float2bfloat16(0.f); }
    }

    // final barrier: cover in-flight remote ops before any CTA exits
    asm volatile("barrier.cluster.arrive.aligned;" ::: "memory");
    asm volatile("barrier.cluster.wait.aligned;" ::: "memory");
}

// ---------------- emissions -----------------------------------------------------
__global__ void k_emis(const float* __restrict__ fc_w, const float* __restrict__ fc_b) {
    int w = blockIdx.x * 8 + (threadIdx.x >> 5);
    int lane = threadIdx.x & 31;
    int j = lane < NT_ ? lane : 0;
    const float* x = g_xA + (size_t)w * E_;
    float acc = fc_b[j];
#pragma unroll 4
    for (int k = 0; k < E_; k += 4) {
        float4 xv = *(const float4*)(x + k);
        acc += xv.x * fc_w[(k + 0) * NT_ + j] + xv.y * fc_w[(k + 1) * NT_ + j]
             + xv.z * fc_w[(k + 2) * NT_ + j] + xv.w * fc_w[(k + 3) * NT_ + j];
    }
    if (lane < NT_) g_em[(size_t)w * NT_ + lane] = acc;
}

// ---------------- CRF -----------------------------------------------------------
__global__ void k_crf(const int* __restrict__ tags, const int* __restrict__ lengths,
                      const float* __restrict__ crf_start, const float* __restrict__ crf_end,
                      const float* __restrict__ crf_trans) {
    int b = blockIdx.x;
    int lane = threadIdx.x;
    int len = lengths[b];
    const int* tg = tags + b * T_;
    const float* em = g_em + (size_t)b * T_ * NT_;

    float part = 0.f;
    for (int t = lane; t < T_; t += 32) {
        if (t < len) {
            int tt = tg[t];
            part += em[t * NT_ + tt];
            if (t >= 1) part += crf_trans[tg[t - 1] * NT_ + tt];
        }
    }
#pragma unroll
    for (int o = 16; o; o >>= 1) part += __shfl_xor_sync(0xFFFFFFFFu, part, o);
    float numer = part + crf_start[tg[0]] + crf_end[tg[len - 1]];

    int j = lane < NT_ ? lane : 0;
    float etr[NT_];
#pragma unroll
    for (int i = 0; i < NT_; i++) etr[i] = expf(crf_trans[i * NT_ + j]);

    float s = crf_start[j] + em[j];
    for (int t = 1; t < len; ++t) {
        float sl = (lane < NT_) ? s : -1e30f;
        float m = sl;
#pragma unroll
        for (int o = 16; o; o >>= 1) m = fmaxf(m, __shfl_xor_sync(0xFFFFFFFFu, m, o));
        float es = expf(s - m);
        float z = 0.f;
#pragma unroll
        for (int i = 0; i < NT_; i++) {
            float ei = __shfl_sync(0xFFFFFFFFu, es, i);
            z += ei * etr[i];
        }
        s = m + logf(z) + em[t * NT_ + j];
    }
    s += crf_end[j];
    float sj = (lane < NT_) ? s : -1e30f;
    float mm = sj;
#pragma unroll
    for (int o = 16; o; o >>= 1) mm = fmaxf(mm, __shfl_xor_sync(0xFFFFFFFFu, mm, o));
    float zz = (lane < NT_) ? expf(sj - mm) : 0.f;
#pragma unroll
    for (int o = 16; o; o >>= 1) zz += __shfl_xor_sync(0xFFFFFFFFu, zz, o);
    float logZ = mm + logf(zz);
    if (lane == 0) g_llh[b] = numer - logZ;
}

// ---------------- final reduction ----------------------------------------------
__global__ void k_reduce(float* __restrict__ out) {
    int lane = threadIdx.x;
    float v = g_llh[lane];
    __shared__ float tmp[2];
#pragma unroll
    for (int o = 16; o; o >>= 1) v += __shfl_xor_sync(0xFFFFFFFFu, v, o);
    if ((lane & 31) == 0) tmp[lane >> 5] = v;
    __syncthreads();
    if (lane == 0) out[0] = -(tmp[0] + tmp[1]);
}

// ---------------- host launcher -------------------------------------------------
extern "C" void kernel_launch(void* const* d_in, const int* in_sizes, int n_in,
                              void* d_out, int out_size) {
    const int*   ids   = (const int*)d_in[0];
    const int*   lens  = (const int*)d_in[1];
    const int*   tags  = (const int*)d_in[2];
    const float* embed = (const float*)d_in[3];
    const float* w_ih  = (const float*)d_in[4];
    const float* w_hh  = (const float*)d_in[5];
    const float* b_ih  = (const float*)d_in[6];
    const float* b_hh  = (const float*)d_in[7];
    const float* fc_w  = (const float*)d_in[8];
    const float* fc_b  = (const float*)d_in[9];
    const float* c_st  = (const float*)d_in[10];
    const float* c_en  = (const float*)d_in[11];
    const float* c_tr  = (const float*)d_in[12];
    float* out = (float*)d_out;

    k_wcvt<<<2048, 256>>>(w_ih);                       // 0
    k_gather<<<B_ * T_, 128>>>(ids, embed);            // 1
    k_gemm_bf<<<dim3(16, 256), 256>>>(b_ih, b_hh, 0);  // 2
    k_lstm<<<32, 256>>>(w_hh, lens, 0, 0);             // 3
    k_gemm_bf<<<dim3(16, 256), 256>>>(b_ih, b_hh, 1);  // 4
    k_lstm<<<32, 256>>>(w_hh, lens, 1, 1);             // 5  <- profiled
    k_emis<<<B_ * T_ / 8, 256>>>(fc_w, fc_b);          // 6
    k_crf<<<B_, 32>>>(tags, lens, c_st, c_en, c_tr);   // 7
    k_reduce<<<1, 64>>>(out);                          // 8
}

// round 11
// speedup vs baseline: 1.0539x; 1.0539x over previous
#include <cuda_runtime.h>
#include <cuda_bf16.h>
#include <stdint.h>
#include <math.h>

#define B_  64
#define T_  512
#define E_  512
#define H_  256
#define NT_ 20
#define HBUF (16 * 264 * 2)   /* bytes per h buffer */

// ---------------- scratch (device globals) ------------------------------------
__device__ __nv_bfloat16 g_xbfA[B_ * T_ * E_];        // 32 MB  layer-0 input (bf16)
__device__ __nv_bfloat16 g_xbfB[B_ * T_ * E_];        // 32 MB  layer-1 input (bf16)
__device__ float g_xA[B_ * T_ * E_];                  // 64 MB  final layer output (fp32)
__device__ float g_xg[(size_t)B_ * T_ * 2048];        // 256 MB input projections
__device__ __nv_bfloat16 g_wbf[2 * 2048 * E_];        // 4 MB   w_ih in bf16
__device__ float g_em[B_ * T_ * NT_];
__device__ float g_llh[B_];

// ---------------- small helpers ------------------------------------------------
__device__ __forceinline__ unsigned pack_bf2(float a, float b) {
    __nv_bfloat162 h2 = __floats2bfloat162_rn(a, b);
    return *reinterpret_cast<unsigned*>(&h2);
}
__device__ __forceinline__ void ldsm4(unsigned& a0, unsigned& a1, unsigned& a2, unsigned& a3,
                                      unsigned addr) {
    asm volatile("ldmatrix.sync.aligned.m8n8.x4.shared.b16 {%0,%1,%2,%3}, [%4];\n"
                 : "=r"(a0), "=r"(a1), "=r"(a2), "=r"(a3) : "r"(addr));
}
__device__ __forceinline__ void mma_bf(float& d0, float& d1, float& d2, float& d3,
                                       unsigned a0, unsigned a1, unsigned a2, unsigned a3,
                                       unsigned b0, unsigned b1) {
    asm volatile("mma.sync.aligned.m16n8k16.row.col.f32.bf16.bf16.f32 "
                 "{%0,%1,%2,%3},{%4,%5,%6,%7},{%8,%9},{%0,%1,%2,%3};\n"
                 : "+f"(d0), "+f"(d1), "+f"(d2), "+f"(d3)
                 : "r"(a0), "r"(a1), "r"(a2), "r"(a3), "r"(b0), "r"(b1));
}
__device__ __forceinline__ unsigned mapa_u32(unsigned addr, int rank) {
    unsigned out;
    asm("mapa.shared::cluster.u32 %0, %1, %2;" : "=r"(out) : "r"(addr), "r"(rank));
    return out;
}
__device__ __forceinline__ void st_dsm64(unsigned addr, unsigned long long v) {
    asm volatile("st.shared::cluster.b64 [%0], %1;" :: "r"(addr), "l"(v) : "memory");
}
__device__ __forceinline__ float tanhfast(float x) {
    float y;
    asm("tanh.approx.f32 %0, %1;" : "=f"(y) : "f"(x));
    return y;
}
__device__ __forceinline__ float sigm(float x) { return 0.5f * tanhfast(0.5f * x) + 0.5f; }

// ---------------- conversion / gather ------------------------------------------
__global__ void k_wcvt(const float* __restrict__ w_ih) {
    int i = (blockIdx.x * 256 + threadIdx.x) * 4;
    float4 v = *(const float4*)(w_ih + i);
    uint2 o;
    o.x = pack_bf2(v.x, v.y);
    o.y = pack_bf2(v.z, v.w);
    *(uint2*)(g_wbf + i) = o;
}

__global__ void k_gather(const int* __restrict__ ids, const float* __restrict__ embed) {
    int bt = blockIdx.x;
    int id = ids[bt];
    int e = threadIdx.x * 4;
    float4 v = *(const float4*)(embed + (size_t)id * E_ + e);
    uint2 o;
    o.x = pack_bf2(v.x, v.y);
    o.y = pack_bf2(v.z, v.w);
    *(uint2*)(g_xbfA + (size_t)bt * E_ + e) = o;
}

// ---------------- bf16 tensor-core GEMM: xg = X @ W^T + bias -------------------
__global__ void __launch_bounds__(256) k_gemm_bf(const float* __restrict__ b_ih,
                                                 const float* __restrict__ b_hh,
                                                 int layer) {
    __shared__ __align__(16) __nv_bfloat16 As[128 * 40];
    __shared__ __align__(16) __nv_bfloat16 Bs[128 * 40];

    const __nv_bfloat16* Xbf = layer ? g_xbfB : g_xbfA;
    const __nv_bfloat16* Wbf = g_wbf + (size_t)layer * 2048 * E_;
    const float* bi = b_ih + layer * 2048;
    const float* bh = b_hh + layer * 2048;

    int m0 = blockIdx.y * 128, n0 = blockIdx.x * 128;
    int tid = threadIdx.x, w = tid >> 5, lane = tid & 31;

    const __nv_bfloat16* Ag = Xbf + (size_t)(m0 + (tid >> 2)) * E_ + (tid & 3) * 8;
    const __nv_bfloat16* Bg = Wbf + (size_t)(n0 + (tid >> 2)) * E_ + (tid & 3) * 8;
    int soff = (tid >> 2) * 40 + (tid & 3) * 8;

    unsigned a_base = (unsigned)__cvta_generic_to_shared(As);
    unsigned b_base = (unsigned)__cvta_generic_to_shared(Bs);

    int mbase = (w & 1) * 64, nbase = (w >> 1) * 32;

    float acc[4][4][4];
#pragma unroll
    for (int i = 0; i < 4; i++)
#pragma unroll
        for (int j = 0; j < 4; j++)
#pragma unroll
            for (int r = 0; r < 4; r++) acc[i][j][r] = 0.f;

    uint4 ra[2], rb[2];
#pragma unroll
    for (int i = 0; i < 2; i++) {
        ra[i] = *(const uint4*)(Ag + i * 64 * E_);
        rb[i] = *(const uint4*)(Bg + i * 64 * E_);
    }

    for (int kb = 0; kb < 16; ++kb) {
#pragma unroll
        for (int i = 0; i < 2; i++) {
            *(uint4*)&As[soff + i * 64 * 40] = ra[i];
            *(uint4*)&Bs[soff + i * 64 * 40] = rb[i];
        }
        __syncthreads();
        if (kb < 15) {
#pragma unroll
            for (int i = 0; i < 2; i++) {
                ra[i] = *(const uint4*)(Ag + (kb + 1) * 32 + i * 64 * E_);
                rb[i] = *(const uint4*)(Bg + (kb + 1) * 32 + i * 64 * E_);
            }
        }
#pragma unroll
        for (int kk = 0; kk < 32; kk += 16) {
            unsigned aF[4][4], bF[4][2];
#pragma unroll
            for (int mt = 0; mt < 4; ++mt) {
                int row = mbase + mt * 16 + (lane & 15);
                int col = kk + ((lane >> 4) << 3);
                ldsm4(aF[mt][0], aF[mt][1], aF[mt][2], aF[mt][3],
                      a_base + (unsigned)(row * 40 + col) * 2);
            }
#pragma unroll
            for (int p = 0; p < 2; ++p) {
                int row = nbase + 16 * p + ((lane >> 4) << 3) + (lane & 7);
                int colb = kk + (((lane >> 3) & 1) << 3);
                ldsm4(bF[2 * p][0], bF[2 * p][1], bF[2 * p + 1][0], bF[2 * p + 1][1],
                      b_base + (unsigned)(row * 40 + colb) * 2);
            }
#pragma unroll
            for (int mt = 0; mt < 4; ++mt)
#pragma unroll
                for (int nt = 0; nt < 4; ++nt)
                    mma_bf(acc[mt][nt][0], acc[mt][nt][1], acc[mt][nt][2], acc[mt][nt][3],
                           aF[mt][0], aF[mt][1], aF[mt][2], aF[mt][3],
                           bF[nt][0], bF[nt][1]);
        }
        __syncthreads();
    }

#pragma unroll
    for (int nt = 0; nt < 4; ++nt) {
        int coln = n0 + nbase + 8 * nt + 2 * (lane & 3);
        float bb0 = bi[coln] + bh[coln];
        float bb1 = bi[coln + 1] + bh[coln + 1];
#pragma unroll
        for (int mt = 0; mt < 4; ++mt) {
            int row = m0 + mbase + 16 * mt + (lane >> 2);
            *(float2*)&g_xg[(size_t)row * 2048 + coln] =
                make_float2(acc[mt][nt][0] + bb0, acc[mt][nt][1] + bb1);
            *(float2*)&g_xg[(size_t)(row + 8) * 2048 + coln] =
                make_float2(acc[mt][nt][2] + bb0, acc[mt][nt][3] + bb1);
        }
    }
}

// ---------------- persistent BiLSTM layer: dirs split across warps -------------
// 32 CTAs (512 thr) = 4 clusters of 8.  Cluster = batch-block of 16, BOTH dirs.
// CTA rank ub owns units [ub*32, ub*32+32) for both dirs.
// Warps 0-7 = dir 0, warps 8-15 = dir 1; warp (dir, w) owns units 4w..4w+3
// with all four gates in its mma D-fragment.  Per-warp register load is
// identical to round 8 (64 B-frag regs) — no spill.  ONE cluster barrier per
// combined step covers both dirs' exchanges.
__global__ void __launch_bounds__(512, 1) __cluster_dims__(8, 1, 1)
k_lstm(const float* __restrict__ w_hh, const int* __restrict__ lengths,
       int layer, int out_fp32) {
    __shared__ __align__(16) __nv_bfloat16 h_shD[4][16 * 264]; // [dir*2+parity]
    __shared__ __align__(16) unsigned long long h_own[2][8][16];
    __shared__ int len_sh[16];

    int cta = blockIdx.x;
    int ub  = cta & 7;          // cluster rank
    int bb  = cta >> 3;         // batch-block 0..3
    int tid = threadIdx.x;
    int wg = tid >> 5, lane = tid & 31;
    int dir = wg >> 3;          // 0 or 1
    int w = wg & 7;             // warp within dir

    // ---- B fragments: warp (dir,w) = units {4w..4w+3} x gates {0..3} ----
    unsigned bfr[16][2][2];
    {
        int c2 = (lane & 3) * 2;
#pragma unroll
        for (int p = 0; p < 2; ++p) {
            int lc = 8 * p + (lane >> 2);
            int g = lc & 3, du = lc >> 2;
            const float* wr = w_hh +
                ((size_t)((layer * 2 + dir) * 1024 + g * 256 + ub * 32 + w * 4 + du)) * 256;
#pragma unroll
            for (int kt = 0; kt < 16; ++kt) {
                bfr[kt][p][0] = pack_bf2(wr[kt * 16 + c2],     wr[kt * 16 + c2 + 1]);
                bfr[kt][p][1] = pack_bf2(wr[kt * 16 + c2 + 8], wr[kt * 16 + c2 + 9]);
            }
        }
    }
    if (tid < 16) len_sh[tid] = lengths[bb * 16 + tid];
    // zero step-0 h state for both dirs (parity 0 buffers)
    for (int i = tid; i < 16 * 264 / 2; i += 512) {
        ((unsigned*)h_shD[0])[i] = 0u;
        ((unsigned*)h_shD[2])[i] = 0u;
    }
    __syncthreads();
    asm volatile("barrier.cluster.arrive.aligned;" ::: "memory");
    asm volatile("barrier.cluster.wait.aligned;" ::: "memory");

    int maxlen = 0;
#pragma unroll
    for (int i = 0; i < 16; i++) maxlen = max(maxlen, len_sh[i]);

    // gate mapping: thread (w, lane) -> batches r, r+8 ; unit 4w + du
    int q = lane & 3, r = lane >> 2;
    bool qe = (q & 1) == 0;
    int du = ((q & 1) << 1) | (q >> 1);
    int unit = ub * 32 + 4 * w + du;
    int len0 = len_sh[r], len1 = len_sh[r + 8];
    int gb0 = bb * 16 + r, gb1 = bb * 16 + r + 8;
    const float* xg0p = g_xg + (size_t)gb0 * T_ * 2048 + dir * 1024 + unit;
    const float* xg1p = g_xg + (size_t)gb1 * T_ * 2048 + dir * 1024 + unit;

    unsigned hsh_base = (unsigned)__cvta_generic_to_shared(&h_shD[0][0]);
    unsigned a_addr0 = hsh_base + (unsigned)(2 * dir) * HBUF
                     + (unsigned)(lane & 15) * 528 + ((lane >> 4) << 4);

    // push: lane's FIXED peer = lane&7; batches (lane>>3)+{0,4,8,12}
    int peer = lane & 7;
    unsigned dsm_peer = mapa_u32(hsh_base + (unsigned)(2 * dir) * HBUF
                                 + (unsigned)((ub * 32 + 4 * w) * 2), peer);

    float cst0 = 0.f, cst1 = 0.f;
    float xa[2][8];

    // prefetch xg for s = 0 (this dir)
    {
        int pos0 = dir ? (len0 - 1) : 0;
        int pos1 = dir ? (len1 - 1) : 0;
        const float* p0 = xg0p + (size_t)pos0 * 2048;
        const float* p1 = xg1p + (size_t)pos1 * 2048;
        xa[0][0] = p0[0]; xa[0][1] = p0[256]; xa[0][2] = p0[512]; xa[0][3] = p0[768];
        xa[0][4] = p1[0]; xa[0][5] = p1[256]; xa[0][6] = p1[512]; xa[0][7] = p1[768];
    }

    for (int s = 0; s < maxlen; ++s) {
        int p = s & 1;
        // ---- prefetch xg for s+1 (issues before the barrier wait) ----
        if (s + 1 < maxlen) {
            int sn = s + 1;
            if (sn < len0) {
                int pos0 = dir ? (len0 - 1 - sn) : sn;
                const float* pp = xg0p + (size_t)pos0 * 2048;
                xa[p ^ 1][0] = pp[0]; xa[p ^ 1][1] = pp[256];
                xa[p ^ 1][2] = pp[512]; xa[p ^ 1][3] = pp[768];
            }
            if (sn < len1) {
                int pos1 = dir ? (len1 - 1 - sn) : sn;
                const float* pp = xg1p + (size_t)pos1 * 2048;
                xa[p ^ 1][4] = pp[0]; xa[p ^ 1][5] = pp[256];
                xa[p ^ 1][6] = pp[512]; xa[p ^ 1][7] = pp[768];
            }
        }

        // ---- wait: peers' pushes from step s-1 landed (both dirs) ----
        if (s > 0)
            asm volatile("barrier.cluster.wait.aligned;" ::: "memory");

        // ---- recurrent mma (this dir), split even/odd chains ----
        unsigned a_addr = a_addr0 + (unsigned)p * HBUF;
        float aA[2][4], aB[2][4];
#pragma unroll
        for (int t = 0; t < 2; ++t)
#pragma unroll
            for (int i = 0; i < 4; ++i) { aA[t][i] = 0.f; aB[t][i] = 0.f; }
#pragma unroll
        for (int kt = 0; kt < 16; kt += 2) {
            unsigned A0, A1, A2, A3;
            ldsm4(A0, A1, A2, A3, a_addr + kt * 32);
            mma_bf(aA[0][0], aA[0][1], aA[0][2], aA[0][3],
                   A0, A1, A2, A3, bfr[kt][0][0], bfr[kt][0][1]);
            mma_bf(aA[1][0], aA[1][1], aA[1][2], aA[1][3],
                   A0, A1, A2, A3, bfr[kt][1][0], bfr[kt][1][1]);
            unsigned B0, B1, B2, B3;
            ldsm4(B0, B1, B2, B3, a_addr + (kt + 1) * 32);
            mma_bf(aB[0][0], aB[0][1], aB[0][2], aB[0][3],
                   B0, B1, B2, B3, bfr[kt + 1][0][0], bfr[kt + 1][0][1]);
            mma_bf(aB[1][0], aB[1][1], aB[1][2], aB[1][3],
                   B0, B1, B2, B3, bfr[kt + 1][1][0], bfr[kt + 1][1][1]);
        }
        float acc0[4], acc1[4];
#pragma unroll
        for (int i = 0; i < 4; ++i) { acc0[i] = aA[0][i] + aB[0][i];
                                      acc1[i] = aA[1][i] + aB[1][i]; }

        // ---- lane-pair exchange: swap the "other" ntile with partner ----
        float own[4], rcv[4];
#pragma unroll
        for (int i = 0; i < 4; ++i) {
            float snd = qe ? acc1[i] : acc0[i];
            rcv[i] = __shfl_xor_sync(0xFFFFFFFFu, snd, 1);
            own[i] = qe ? acc0[i] : acc1[i];
        }
        float ai0 = (qe ? own[0] : rcv[0]) + xa[p][0];
        float af0 = (qe ? own[1] : rcv[1]) + xa[p][1];
        float ag0 = (qe ? rcv[0] : own[0]) + xa[p][2];
        float ao0 = (qe ? rcv[1] : own[1]) + xa[p][3];
        float ai1 = (qe ? own[2] : rcv[2]) + xa[p][4];
        float af1 = (qe ? own[3] : rcv[3]) + xa[p][5];
        float ag1 = (qe ? rcv[2] : own[2]) + xa[p][6];
        float ao1 = (qe ? rcv[3] : own[3]) + xa[p][7];

        bool v0 = s < len0, v1 = s < len1;
        float hv0 = 0.f, hv1 = 0.f;
        if (v0) {
            cst0 = sigm(af0) * cst0 + sigm(ai0) * tanhfast(ag0);
            hv0 = sigm(ao0) * tanhfast(cst0);
            ((__nv_bfloat16*)&h_own[dir][w][r])[du] = __float2bfloat16(hv0);
        }
        if (v1) {
            cst1 = sigm(af1) * cst1 + sigm(ai1) * tanhfast(ag1);
            hv1 = sigm(ao1) * tanhfast(cst1);
            ((__nv_bfloat16*)&h_own[dir][w][r + 8])[du] = __float2bfloat16(hv1);
        }
        __syncwarp();

        // ---- push own slice to every peer; ONE arrive per combined step ----
        if (s + 1 < maxlen) {
            unsigned dbase = dsm_peer + (unsigned)(p ^ 1) * HBUF;
#pragma unroll
            for (int j = 0; j < 4; ++j) {
                int batch = (lane >> 3) + 4 * j;
                st_dsm64(dbase + (unsigned)batch * 528, h_own[dir][w][batch]);
            }
            asm volatile("barrier.cluster.arrive.aligned;" ::: "memory");
        }

        // ---- off critical path: write layer output ----
        if (v0) {
            int pos0 = dir ? (len0 - 1 - s) : s;
            size_t xoff = ((size_t)gb0 * T_ + pos0) * E_ + dir * H_ + unit;
            if (out_fp32) g_xA[xoff] = hv0; else g_xbfB[xoff] = __float2bfloat16(hv0);
        }
        if (v1) {
            int pos1 = dir ? (len1 - 1 - s) : s;
            size_t xoff = ((size_t)gb1 * T_ + pos1) * E_ + dir * H_ + unit;
            if (out_fp32) g_xA[xoff] = hv1; else g_xbfB[xoff] = __float2bfloat16(hv1);
        }
    }

    // ---- fused tail zeroing: positions t in [len, T), this dir ----
    for (int t = len0; t < T_; ++t) {
        size_t xoff = ((size_t)gb0 * T_ + t) * E_ + dir * H_ + unit;
        if (out_fp32) g_xA[xoff] = 0.f; else g_xbfB[xoff] = __float2bfloat16(0.f);
    }
    for (int t = len1; t < T_; ++t) {
        size_t xoff = ((size_t)gb1 * T_ + t) * E_ + dir * H_ + unit;
        if (out_fp32) g_xA[xoff] = 0.f; else g_xbfB[xoff] = __float2bfloat16(0.f);
    }

    // final barrier: cover in-flight remote ops before any CTA exits
    asm volatile("barrier.cluster.arrive.aligned;" ::: "memory");
    asm volatile("barrier.cluster.wait.aligned;" ::: "memory");
}

// ---------------- emissions -----------------------------------------------------
__global__ void k_emis(const float* __restrict__ fc_w, const float* __restrict__ fc_b) {
    int w = blockIdx.x * 8 + (threadIdx.x >> 5);
    int lane = threadIdx.x & 31;
    int j = lane < NT_ ? lane : 0;
    const float* x = g_xA + (size_t)w * E_;
    float acc = fc_b[j];
#pragma unroll 4
    for (int k = 0; k < E_; k += 4) {
        float4 xv = *(const float4*)(x + k);
        acc += xv.x * fc_w[(k + 0) * NT_ + j] + xv.y * fc_w[(k + 1) * NT_ + j]
             + xv.z * fc_w[(k + 2) * NT_ + j] + xv.w * fc_w[(k + 3) * NT_ + j];
    }
    if (lane < NT_) g_em[(size_t)w * NT_ + lane] = acc;
}

// ---------------- CRF -----------------------------------------------------------
__global__ void k_crf(const int* __restrict__ tags, const int* __restrict__ lengths,
                      const float* __restrict__ crf_start, const float* __restrict__ crf_end,
                      const float* __restrict__ crf_trans) {
    int b = blockIdx.x;
    int lane = threadIdx.x;
    int len = lengths[b];
    const int* tg = tags + b * T_;
    const float* em = g_em + (size_t)b * T_ * NT_;

    float part = 0.f;
    for (int t = lane; t < T_; t += 32) {
        if (t < len) {
            int tt = tg[t];
            part += em[t * NT_ + tt];
            if (t >= 1) part += crf_trans[tg[t - 1] * NT_ + tt];
        }
    }
#pragma unroll
    for (int o = 16; o; o >>= 1) part += __shfl_xor_sync(0xFFFFFFFFu, part, o);
    float numer = part + crf_start[tg[0]] + crf_end[tg[len - 1]];

    int j = lane < NT_ ? lane : 0;
    float etr[NT_];
#pragma unroll
    for (int i = 0; i < NT_; i++) etr[i] = expf(crf_trans[i * NT_ + j]);

    float s = crf_start[j] + em[j];
    for (int t = 1; t < len; ++t) {
        float sl = (lane < NT_) ? s : -1e30f;
        float m = sl;
#pragma unroll
        for (int o = 16; o; o >>= 1) m = fmaxf(m, __shfl_xor_sync(0xFFFFFFFFu, m, o));
        float es = expf(s - m);
        float z = 0.f;
#pragma unroll
        for (int i = 0; i < NT_; i++) {
            float ei = __shfl_sync(0xFFFFFFFFu, es, i);
            z += ei * etr[i];
        }
        s = m + logf(z) + em[t * NT_ + j];
    }
    s += crf_end[j];
    float sj = (lane < NT_) ? s : -1e30f;
    float mm = sj;
#pragma unroll
    for (int o = 16; o; o >>= 1) mm = fmaxf(mm, __shfl_xor_sync(0xFFFFFFFFu, mm, o));
    float zz = (lane < NT_) ? expf(sj - mm) : 0.f;
#pragma unroll
    for (int o = 16; o; o >>= 1) zz += __shfl_xor_sync(0xFFFFFFFFu, zz, o);
    float logZ = mm + logf(zz);
    if (lane == 0) g_llh[b] = numer - logZ;
}

// ---------------- final reduction ----------------------------------------------
__global__ void k_reduce(float* __restrict__ out) {
    int lane = threadIdx.x;
    float v = g_llh[lane];
    __shared__ float tmp[2];
#pragma unroll
    for (int o = 16; o; o >>= 1) v += __shfl_xor_sync(0xFFFFFFFFu, v, o);
    if ((lane & 31) == 0) tmp[lane >> 5] = v;
    __syncthreads();
    if (lane == 0) out[0] = -(tmp[0] + tmp[1]);
}

// ---------------- host launcher -------------------------------------------------
extern "C" void kernel_launch(void* const* d_in, const int* in_sizes, int n_in,
                              void* d_out, int out_size) {
    const int*   ids   = (const int*)d_in[0];
    const int*   lens  = (const int*)d_in[1];
    const int*   tags  = (const int*)d_in[2];
    const float* embed = (const float*)d_in[3];
    const float* w_ih  = (const float*)d_in[4];
    const float* w_hh  = (const float*)d_in[5];
    const float* b_ih  = (const float*)d_in[6];
    const float* b_hh  = (const float*)d_in[7];
    const float* fc_w  = (const float*)d_in[8];
    const float* fc_b  = (const float*)d_in[9];
    const float* c_st  = (const float*)d_in[10];
    const float* c_en  = (const float*)d_in[11];
    const float* c_tr  = (const float*)d_in[12];
    float* out = (float*)d_out;

    k_wcvt<<<2048, 256>>>(w_ih);                       // 0
    k_gather<<<B_ * T_, 128>>>(ids, embed);            // 1
    k_gemm_bf<<<dim3(16, 256), 256>>>(b_ih, b_hh, 0);  // 2
    k_lstm<<<32, 512>>>(w_hh, lens, 0, 0);             // 3
    k_gemm_bf<<<dim3(16, 256), 256>>>(b_ih, b_hh, 1);  // 4
    k_lstm<<<32, 512>>>(w_hh, lens, 1, 1);             // 5  <- profiled
    k_emis<<<B_ * T_ / 8, 256>>>(fc_w, fc_b);          // 6
    k_crf<<<B_, 32>>>(tags, lens, c_st, c_en, c_tr);   // 7
    k_reduce<<<1, 64>>>(out);                          // 8
}

// round 12
// speedup vs baseline: 1.2705x; 1.2055x over previous
#include <cuda_runtime.h>
#include <cuda_bf16.h>
#include <stdint.h>
#include <math.h>

#define B_  64
#define T_  512
#define E_  512
#define H_  256
#define NT_ 20
#define HBUF (16 * 264 * 2)   /* bytes per h buffer */

// ---------------- scratch (device globals) ------------------------------------
__device__ __nv_bfloat16 g_xbfA[B_ * T_ * E_];        // 32 MB  layer-0 input (bf16)
__device__ __nv_bfloat16 g_xbfB[B_ * T_ * E_];        // 32 MB  layer-1 input (bf16)
__device__ float g_xA[B_ * T_ * E_];                  // 64 MB  final layer output (fp32)
__device__ float g_xg[(size_t)B_ * T_ * 2048];        // 256 MB input projections
__device__ __nv_bfloat16 g_wbf[2 * 2048 * E_];        // 4 MB   w_ih in bf16
__device__ float g_em[B_ * T_ * NT_];
__device__ float g_llh[B_];

// ---------------- small helpers ------------------------------------------------
__device__ __forceinline__ unsigned pack_bf2(float a, float b) {
    __nv_bfloat162 h2 = __floats2bfloat162_rn(a, b);
    return *reinterpret_cast<unsigned*>(&h2);
}
__device__ __forceinline__ void ldsm4(unsigned& a0, unsigned& a1, unsigned& a2, unsigned& a3,
                                      unsigned addr) {
    asm volatile("ldmatrix.sync.aligned.m8n8.x4.shared.b16 {%0,%1,%2,%3}, [%4];\n"
                 : "=r"(a0), "=r"(a1), "=r"(a2), "=r"(a3) : "r"(addr));
}
__device__ __forceinline__ void mma_bf(float& d0, float& d1, float& d2, float& d3,
                                       unsigned a0, unsigned a1, unsigned a2, unsigned a3,
                                       unsigned b0, unsigned b1) {
    asm volatile("mma.sync.aligned.m16n8k16.row.col.f32.bf16.bf16.f32 "
                 "{%0,%1,%2,%3},{%4,%5,%6,%7},{%8,%9},{%0,%1,%2,%3};\n"
                 : "+f"(d0), "+f"(d1), "+f"(d2), "+f"(d3)
                 : "r"(a0), "r"(a1), "r"(a2), "r"(a3), "r"(b0), "r"(b1));
}
__device__ __forceinline__ unsigned mapa_u32(unsigned addr, int rank) {
    unsigned out;
    asm("mapa.shared::cluster.u32 %0, %1, %2;" : "=r"(out) : "r"(addr), "r"(rank));
    return out;
}
__device__ __forceinline__ void st_dsm64(unsigned addr, unsigned long long v) {
    asm volatile("st.shared::cluster.b64 [%0], %1;" :: "r"(addr), "l"(v) : "memory");
}
__device__ __forceinline__ float tanhfast(float x) {
    float y;
    asm("tanh.approx.f32 %0, %1;" : "=f"(y) : "f"(x));
    return y;
}
__device__ __forceinline__ float sigm(float x) { return 0.5f * tanhfast(0.5f * x) + 0.5f; }

// ---------------- conversion / gather ------------------------------------------
__global__ void k_wcvt(const float* __restrict__ w_ih) {
    int i = (blockIdx.x * 256 + threadIdx.x) * 4;
    float4 v = *(const float4*)(w_ih + i);
    uint2 o;
    o.x = pack_bf2(v.x, v.y);
    o.y = pack_bf2(v.z, v.w);
    *(uint2*)(g_wbf + i) = o;
}

__global__ void k_gather(const int* __restrict__ ids, const float* __restrict__ embed) {
    int bt = blockIdx.x;
    int id = ids[bt];
    int e = threadIdx.x * 4;
    float4 v = *(const float4*)(embed + (size_t)id * E_ + e);
    uint2 o;
    o.x = pack_bf2(v.x, v.y);
    o.y = pack_bf2(v.z, v.w);
    *(uint2*)(g_xbfA + (size_t)bt * E_ + e) = o;
}

// ---------------- bf16 tensor-core GEMM: xg = X @ W^T + bias -------------------
__global__ void __launch_bounds__(256) k_gemm_bf(const float* __restrict__ b_ih,
                                                 const float* __restrict__ b_hh,
                                                 int layer) {
    __shared__ __align__(16) __nv_bfloat16 As[128 * 40];
    __shared__ __align__(16) __nv_bfloat16 Bs[128 * 40];

    const __nv_bfloat16* Xbf = layer ? g_xbfB : g_xbfA;
    const __nv_bfloat16* Wbf = g_wbf + (size_t)layer * 2048 * E_;
    const float* bi = b_ih + layer * 2048;
    const float* bh = b_hh + layer * 2048;

    int m0 = blockIdx.y * 128, n0 = blockIdx.x * 128;
    int tid = threadIdx.x, w = tid >> 5, lane = tid & 31;

    const __nv_bfloat16* Ag = Xbf + (size_t)(m0 + (tid >> 2)) * E_ + (tid & 3) * 8;
    const __nv_bfloat16* Bg = Wbf + (size_t)(n0 + (tid >> 2)) * E_ + (tid & 3) * 8;
    int soff = (tid >> 2) * 40 + (tid & 3) * 8;

    unsigned a_base = (unsigned)__cvta_generic_to_shared(As);
    unsigned b_base = (unsigned)__cvta_generic_to_shared(Bs);

    int mbase = (w & 1) * 64, nbase = (w >> 1) * 32;

    float acc[4][4][4];
#pragma unroll
    for (int i = 0; i < 4; i++)
#pragma unroll
        for (int j = 0; j < 4; j++)
#pragma unroll
            for (int r = 0; r < 4; r++) acc[i][j][r] = 0.f;

    uint4 ra[2], rb[2];
#pragma unroll
    for (int i = 0; i < 2; i++) {
        ra[i] = *(const uint4*)(Ag + i * 64 * E_);
        rb[i] = *(const uint4*)(Bg + i * 64 * E_);
    }

    for (int kb = 0; kb < 16; ++kb) {
#pragma unroll
        for (int i = 0; i < 2; i++) {
            *(uint4*)&As[soff + i * 64 * 40] = ra[i];
            *(uint4*)&Bs[soff + i * 64 * 40] = rb[i];
        }
        __syncthreads();
        if (kb < 15) {
#pragma unroll
            for (int i = 0; i < 2; i++) {
                ra[i] = *(const uint4*)(Ag + (kb + 1) * 32 + i * 64 * E_);
                rb[i] = *(const uint4*)(Bg + (kb + 1) * 32 + i * 64 * E_);
            }
        }
#pragma unroll
        for (int kk = 0; kk < 32; kk += 16) {
            unsigned aF[4][4], bF[4][2];
#pragma unroll
            for (int mt = 0; mt < 4; ++mt) {
                int row = mbase + mt * 16 + (lane & 15);
                int col = kk + ((lane >> 4) << 3);
                ldsm4(aF[mt][0], aF[mt][1], aF[mt][2], aF[mt][3],
                      a_base + (unsigned)(row * 40 + col) * 2);
            }
#pragma unroll
            for (int p = 0; p < 2; ++p) {
                int row = nbase + 16 * p + ((lane >> 4) << 3) + (lane & 7);
                int colb = kk + (((lane >> 3) & 1) << 3);
                ldsm4(bF[2 * p][0], bF[2 * p][1], bF[2 * p + 1][0], bF[2 * p + 1][1],
                      b_base + (unsigned)(row * 40 + colb) * 2);
            }
#pragma unroll
            for (int mt = 0; mt < 4; ++mt)
#pragma unroll
                for (int nt = 0; nt < 4; ++nt)
                    mma_bf(acc[mt][nt][0], acc[mt][nt][1], acc[mt][nt][2], acc[mt][nt][3],
                           aF[mt][0], aF[mt][1], aF[mt][2], aF[mt][3],
                           bF[nt][0], bF[nt][1]);
        }
        __syncthreads();
    }

#pragma unroll
    for (int nt = 0; nt < 4; ++nt) {
        int coln = n0 + nbase + 8 * nt + 2 * (lane & 3);
        float bb0 = bi[coln] + bh[coln];
        float bb1 = bi[coln + 1] + bh[coln + 1];
#pragma unroll
        for (int mt = 0; mt < 4; ++mt) {
            int row = m0 + mbase + 16 * mt + (lane >> 2);
            *(float2*)&g_xg[(size_t)row * 2048 + coln] =
                make_float2(acc[mt][nt][0] + bb0, acc[mt][nt][1] + bb1);
            *(float2*)&g_xg[(size_t)(row + 8) * 2048 + coln] =
                make_float2(acc[mt][nt][2] + bb0, acc[mt][nt][3] + bb1);
        }
    }
}

// ---------------- persistent BiLSTM layer: cluster-of-4 ------------------------
// 32 CTAs = 8 clusters of 4.  Cluster = (dir, batch-block of 16).
// CTA rank ub owns units [ub*64, ub*64+64).  Warp w owns units 8w..8w+7 as
// TWO round-8-style pairs (pair t: units 8w+4t..8w+4t+3, all 4 gates).
// Per kt: 1 ldsm (A shared) + 4 mma.  Push to 3 peers; barrier over 4 CTAs.
__global__ void __launch_bounds__(256, 1) __cluster_dims__(4, 1, 1)
k_lstm(const float* __restrict__ w_hh, const int* __restrict__ lengths,
       int layer, int out_fp32) {
    __shared__ __align__(16) __nv_bfloat16 h_shD[2][16 * 264]; // dbl-buffered full h
    __shared__ __align__(16) unsigned long long h_own[8][16][2]; // [warp][batch][2x4units]
    __shared__ int len_sh[16];

    int cta = blockIdx.x;
    int ub  = cta & 3;          // cluster rank
    int grp = cta >> 2;
    int bb  = grp & 3;
    int dir = grp >> 2;
    int tid = threadIdx.x;
    int w = tid >> 5, lane = tid & 31;

    // ---- B fragments: warp w = units {8w..8w+7} x gates {0..3}, 2 pairs ----
    unsigned bfr[16][2][2][2];   // [kt][pair][ntile-in-pair][reg]
    {
        int c2 = (lane & 3) * 2;
#pragma unroll
        for (int t = 0; t < 2; ++t) {
#pragma unroll
            for (int p = 0; p < 2; ++p) {
                int lc = 8 * p + (lane >> 2);
                int g = lc & 3, du = lc >> 2;
                const float* wr = w_hh +
                    ((size_t)((layer * 2 + dir) * 1024 + g * 256 + ub * 64 + w * 8 + 4 * t + du)) * 256;
#pragma unroll
                for (int kt = 0; kt < 16; ++kt) {
                    bfr[kt][t][p][0] = pack_bf2(wr[kt * 16 + c2],     wr[kt * 16 + c2 + 1]);
                    bfr[kt][t][p][1] = pack_bf2(wr[kt * 16 + c2 + 8], wr[kt * 16 + c2 + 9]);
                }
            }
        }
    }
    if (tid < 16) len_sh[tid] = lengths[bb * 16 + tid];
    // zero h_shD[0] (step-0 h state)
    for (int i = tid; i < 16 * 264 / 2; i += 256)
        ((unsigned*)h_shD[0])[i] = 0u;
    __syncthreads();
    asm volatile("barrier.cluster.arrive.aligned;" ::: "memory");
    asm volatile("barrier.cluster.wait.aligned;" ::: "memory");

    int maxlen = 0;
#pragma unroll
    for (int i = 0; i < 16; i++) maxlen = max(maxlen, len_sh[i]);

    // gate mapping: thread (w, lane) -> batches r, r+8 ; units 8w+4t+du
    int q = lane & 3, r = lane >> 2;
    bool qe = (q & 1) == 0;
    int du = ((q & 1) << 1) | (q >> 1);
    int unit0 = ub * 64 + 8 * w + du;        // pair 0
    int unit1 = unit0 + 4;                   // pair 1
    int len0 = len_sh[r], len1 = len_sh[r + 8];
    int gb0 = bb * 16 + r, gb1 = bb * 16 + r + 8;
    const float* xgb0 = g_xg + (size_t)gb0 * T_ * 2048 + dir * 1024;
    const float* xgb1 = g_xg + (size_t)gb1 * T_ * 2048 + dir * 1024;

    unsigned hsh_base = (unsigned)__cvta_generic_to_shared(&h_shD[0][0]);
    unsigned a_addr0 = hsh_base + (unsigned)(lane & 15) * 528 + ((lane >> 4) << 4);

    // push: lane's FIXED peer = lane&3; batches (lane>>2) and (lane>>2)+8
    int peer = lane & 3;
    unsigned dsm_peer = mapa_u32(hsh_base + (unsigned)(ub * 128 + w * 16), peer);

    float cst[2][2] = {{0.f, 0.f}, {0.f, 0.f}};   // [pair][batch-half]
    float xa[2][2][8];                            // [buf][pair][4 gates x 2 batches]

    // prefetch xg for s = 0 (both pairs)
    {
        int pos0 = dir ? (len0 - 1) : 0;
        int pos1 = dir ? (len1 - 1) : 0;
        const float* p0 = xgb0 + (size_t)pos0 * 2048;
        const float* p1 = xgb1 + (size_t)pos1 * 2048;
#pragma unroll
        for (int t = 0; t < 2; ++t) {
            int u = unit0 + 4 * t;
            xa[0][t][0] = p0[u]; xa[0][t][1] = p0[u + 256];
            xa[0][t][2] = p0[u + 512]; xa[0][t][3] = p0[u + 768];
            xa[0][t][4] = p1[u]; xa[0][t][5] = p1[u + 256];
            xa[0][t][6] = p1[u + 512]; xa[0][t][7] = p1[u + 768];
        }
    }

    for (int s = 0; s < maxlen; ++s) {
        int p = s & 1;
        // ---- prefetch xg for s+1 ----
        if (s + 1 < maxlen) {
            int sn = s + 1;
            if (sn < len0) {
                int pos0 = dir ? (len0 - 1 - sn) : sn;
                const float* pp = xgb0 + (size_t)pos0 * 2048;
#pragma unroll
                for (int t = 0; t < 2; ++t) {
                    int u = unit0 + 4 * t;
                    xa[p ^ 1][t][0] = pp[u]; xa[p ^ 1][t][1] = pp[u + 256];
                    xa[p ^ 1][t][2] = pp[u + 512]; xa[p ^ 1][t][3] = pp[u + 768];
                }
            }
            if (sn < len1) {
                int pos1 = dir ? (len1 - 1 - sn) : sn;
                const float* pp = xgb1 + (size_t)pos1 * 2048;
#pragma unroll
                for (int t = 0; t < 2; ++t) {
                    int u = unit0 + 4 * t;
                    xa[p ^ 1][t][4] = pp[u]; xa[p ^ 1][t][5] = pp[u + 256];
                    xa[p ^ 1][t][6] = pp[u + 512]; xa[p ^ 1][t][7] = pp[u + 768];
                }
            }
        }

        // ---- wait: peers' pushes from step s-1 into h_shD[p] landed ----
        if (s > 0)
            asm volatile("barrier.cluster.wait.aligned;" ::: "memory");

        // ---- recurrent mma: 1 ldsm + 4 mma per kt ----
        unsigned a_addr = a_addr0 + (unsigned)p * HBUF;
        float acc[2][2][4];
#pragma unroll
        for (int t = 0; t < 2; ++t)
#pragma unroll
            for (int n = 0; n < 2; ++n)
#pragma unroll
                for (int i = 0; i < 4; ++i) acc[t][n][i] = 0.f;
#pragma unroll
        for (int kt = 0; kt < 16; ++kt) {
            unsigned A0, A1, A2, A3;
            ldsm4(A0, A1, A2, A3, a_addr + kt * 32);
            mma_bf(acc[0][0][0], acc[0][0][1], acc[0][0][2], acc[0][0][3],
                   A0, A1, A2, A3, bfr[kt][0][0][0], bfr[kt][0][0][1]);
            mma_bf(acc[0][1][0], acc[0][1][1], acc[0][1][2], acc[0][1][3],
                   A0, A1, A2, A3, bfr[kt][0][1][0], bfr[kt][0][1][1]);
            mma_bf(acc[1][0][0], acc[1][0][1], acc[1][0][2], acc[1][0][3],
                   A0, A1, A2, A3, bfr[kt][1][0][0], bfr[kt][1][0][1]);
            mma_bf(acc[1][1][0], acc[1][1][1], acc[1][1][2], acc[1][1][3],
                   A0, A1, A2, A3, bfr[kt][1][1][0], bfr[kt][1][1][1]);
        }

        bool v0 = s < len0, v1 = s < len1;
        float hv0[2], hv1[2];
#pragma unroll
        for (int t = 0; t < 2; ++t) {
            // lane-pair exchange within this pair
            float own[4], rcv[4];
#pragma unroll
            for (int i = 0; i < 4; ++i) {
                float snd = qe ? acc[t][1][i] : acc[t][0][i];
                rcv[i] = __shfl_xor_sync(0xFFFFFFFFu, snd, 1);
                own[i] = qe ? acc[t][0][i] : acc[t][1][i];
            }
            float ai0 = (qe ? own[0] : rcv[0]) + xa[p][t][0];
            float af0 = (qe ? own[1] : rcv[1]) + xa[p][t][1];
            float ag0 = (qe ? rcv[0] : own[0]) + xa[p][t][2];
            float ao0 = (qe ? rcv[1] : own[1]) + xa[p][t][3];
            float ai1 = (qe ? own[2] : rcv[2]) + xa[p][t][4];
            float af1 = (qe ? own[3] : rcv[3]) + xa[p][t][5];
            float ag1 = (qe ? rcv[2] : own[2]) + xa[p][t][6];
            float ao1 = (qe ? rcv[3] : own[3]) + xa[p][t][7];
            hv0[t] = 0.f; hv1[t] = 0.f;
            if (v0) {
                cst[t][0] = sigm(af0) * cst[t][0] + sigm(ai0) * tanhfast(ag0);
                hv0[t] = sigm(ao0) * tanhfast(cst[t][0]);
                ((__nv_bfloat16*)&h_own[w][r][t])[du] = __float2bfloat16(hv0[t]);
            }
            if (v1) {
                cst[t][1] = sigm(af1) * cst[t][1] + sigm(ai1) * tanhfast(ag1);
                hv1[t] = sigm(ao1) * tanhfast(cst[t][1]);
                ((__nv_bfloat16*)&h_own[w][r + 8][t])[du] = __float2bfloat16(hv1[t]);
            }
        }
        __syncwarp();

        // ---- push own 8-unit slice (2 batches per lane) to fixed peer ----
        if (s + 1 < maxlen) {
            unsigned dbase = dsm_peer + (unsigned)(p ^ 1) * HBUF;
            int ba = lane >> 2;
#pragma unroll
            for (int j = 0; j < 2; ++j) {
                int batch = ba + 8 * j;
                st_dsm64(dbase + (unsigned)batch * 528,     h_own[w][batch][0]);
                st_dsm64(dbase + (unsigned)batch * 528 + 8, h_own[w][batch][1]);
            }
            asm volatile("barrier.cluster.arrive.aligned;" ::: "memory");
        }

        // ---- off critical path: write layer output ----
        if (v0) {
            int pos0 = dir ? (len0 - 1 - s) : s;
            size_t xoff = ((size_t)gb0 * T_ + pos0) * E_ + dir * H_;
            if (out_fp32) { g_xA[xoff + unit0] = hv0[0]; g_xA[xoff + unit1] = hv0[1]; }
            else { g_xbfB[xoff + unit0] = __float2bfloat16(hv0[0]);
                   g_xbfB[xoff + unit1] = __float2bfloat16(hv0[1]); }
        }
        if (v1) {
            int pos1 = dir ? (len1 - 1 - s) : s;
            size_t xoff = ((size_t)gb1 * T_ + pos1) * E_ + dir * H_;
            if (out_fp32) { g_xA[xoff + unit0] = hv1[0]; g_xA[xoff + unit1] = hv1[1]; }
            else { g_xbfB[xoff + unit0] = __float2bfloat16(hv1[0]);
                   g_xbfB[xoff + unit1] = __float2bfloat16(hv1[1]); }
        }
    }

    // ---- fused tail zeroing: positions t in [len, T) get zeros ----
    for (int t = len0; t < T_; ++t) {
        size_t xoff = ((size_t)gb0 * T_ + t) * E_ + dir * H_;
        if (out_fp32) { g_xA[xoff + unit0] = 0.f; g_xA[xoff + unit1] = 0.f; }
        else { g_xbfB[xoff + unit0] = __float2bfloat16(0.f);
               g_xbfB[xoff + unit1] = __float2bfloat16(0.f); }
    }
    for (int t = len1; t < T_; ++t) {
        size_t xoff = ((size_t)gb1 * T_ + t) * E_ + dir * H_;
        if (out_fp32) { g_xA[xoff + unit0] = 0.f; g_xA[xoff + unit1] = 0.f; }
        else { g_xbfB[xoff + unit0] = __float2bfloat16(0.f);
               g_xbfB[xoff + unit1] = __float2bfloat16(0.f); }
    }

    // final barrier: cover in-flight remote ops before any CTA exits
    asm volatile("barrier.cluster.arrive.aligned;" ::: "memory");
    asm volatile("barrier.cluster.wait.aligned;" ::: "memory");
}

// ---------------- emissions -----------------------------------------------------
__global__ void k_emis(const float* __restrict__ fc_w, const float* __restrict__ fc_b) {
    int w = blockIdx.x * 8 + (threadIdx.x >> 5);
    int lane = threadIdx.x & 31;
    int j = lane < NT_ ? lane : 0;
    const float* x = g_xA + (size_t)w * E_;
    float acc = fc_b[j];
#pragma unroll 4
    for (int k = 0; k < E_; k += 4) {
        float4 xv = *(const float4*)(x + k);
        acc += xv.x * fc_w[(k + 0) * NT_ + j] + xv.y * fc_w[(k + 1) * NT_ + j]
             + xv.z * fc_w[(k + 2) * NT_ + j] + xv.w * fc_w[(k + 3) * NT_ + j];
    }
    if (lane < NT_) g_em[(size_t)w * NT_ + lane] = acc;
}

// ---------------- CRF -----------------------------------------------------------
__global__ void k_crf(const int* __restrict__ tags, const int* __restrict__ lengths,
                      const float* __restrict__ crf_start, const float* __restrict__ crf_end,
                      const float* __restrict__ crf_trans) {
    int b = blockIdx.x;
    int lane = threadIdx.x;
    int len = lengths[b];
    const int* tg = tags + b * T_;
    const float* em = g_em + (size_t)b * T_ * NT_;

    float part = 0.f;
    for (int t = lane; t < T_; t += 32) {
        if (t < len) {
            int tt = tg[t];
            part += em[t * NT_ + tt];
            if (t >= 1) part += crf_trans[tg[t - 1] * NT_ + tt];
        }
    }
#pragma unroll
    for (int o = 16; o; o >>= 1) part += __shfl_xor_sync(0xFFFFFFFFu, part, o);
    float numer = part + crf_start[tg[0]] + crf_end[tg[len - 1]];

    int j = lane < NT_ ? lane : 0;
    float etr[NT_];
#pragma unroll
    for (int i = 0; i < NT_; i++) etr[i] = expf(crf_trans[i * NT_ + j]);

    float s = crf_start[j] + em[j];
    for (int t = 1; t < len; ++t) {
        float sl = (lane < NT_) ? s : -1e30f;
        float m = sl;
#pragma unroll
        for (int o = 16; o; o >>= 1) m = fmaxf(m, __shfl_xor_sync(0xFFFFFFFFu, m, o));
        float es = expf(s - m);
        float z = 0.f;
#pragma unroll
        for (int i = 0; i < NT_; i++) {
            float ei = __shfl_sync(0xFFFFFFFFu, es, i);
            z += ei * etr[i];
        }
        s = m + logf(z) + em[t * NT_ + j];
    }
    s += crf_end[j];
    float sj = (lane < NT_) ? s : -1e30f;
    float mm = sj;
#pragma unroll
    for (int o = 16; o; o >>= 1) mm = fmaxf(mm, __shfl_xor_sync(0xFFFFFFFFu, mm, o));
    float zz = (lane < NT_) ? expf(sj - mm) : 0.f;
#pragma unroll
    for (int o = 16; o; o >>= 1) zz += __shfl_xor_sync(0xFFFFFFFFu, zz, o);
    float logZ = mm + logf(zz);
    if (lane == 0) g_llh[b] = numer - logZ;
}

// ---------------- final reduction ----------------------------------------------
__global__ void k_reduce(float* __restrict__ out) {
    int lane = threadIdx.x;
    float v = g_llh[lane];
    __shared__ float tmp[2];
#pragma unroll
    for (int o = 16; o; o >>= 1) v += __shfl_xor_sync(0xFFFFFFFFu, v, o);
    if ((lane & 31) == 0) tmp[lane >> 5] = v;
    __syncthreads();
    if (lane == 0) out[0] = -(tmp[0] + tmp[1]);
}

// ---------------- host launcher -------------------------------------------------
extern "C" void kernel_launch(void* const* d_in, const int* in_sizes, int n_in,
                              void* d_out, int out_size) {
    const int*   ids   = (const int*)d_in[0];
    const int*   lens  = (const int*)d_in[1];
    const int*   tags  = (const int*)d_in[2];
    const float* embed = (const float*)d_in[3];
    const float* w_ih  = (const float*)d_in[4];
    const float* w_hh  = (const float*)d_in[5];
    const float* b_ih  = (const float*)d_in[6];
    const float* b_hh  = (const float*)d_in[7];
    const float* fc_w  = (const float*)d_in[8];
    const float* fc_b  = (const float*)d_in[9];
    const float* c_st  = (const float*)d_in[10];
    const float* c_en  = (const float*)d_in[11];
    const float* c_tr  = (const float*)d_in[12];
    float* out = (float*)d_out;

    k_wcvt<<<2048, 256>>>(w_ih);                       // 0
    k_gather<<<B_ * T_, 128>>>(ids, embed);            // 1
    k_gemm_bf<<<dim3(16, 256), 256>>>(b_ih, b_hh, 0);  // 2
    k_lstm<<<32, 256>>>(w_hh, lens, 0, 0);             // 3
    k_gemm_bf<<<dim3(16, 256), 256>>>(b_ih, b_hh, 1);  // 4
    k_lstm<<<32, 256>>>(w_hh, lens, 1, 1);             // 5  <- profiled
    k_emis<<<B_ * T_ / 8, 256>>>(fc_w, fc_b);          // 6
    k_crf<<<B_, 32>>>(tags, lens, c_st, c_en, c_tr);   // 7
    k_reduce<<<1, 64>>>(out);                          // 8
}